// round 10
// baseline (speedup 1.0000x reference)
#include <cuda_runtime.h>
#include <cstdint>

#define NQ    32
#define KCB   1024
#define CDIM  8
#define DDIM  1024
#define BDIMS 8
#define TDIM  4096
#define TILE  32
#define NTH   512
#define NCOLS (BDIMS*TDIM)
#define BDT   (BDIMS*DDIM*TDIM)
#define NQBT  (NQ*NCOLS)

/* shared memory offsets (floats) */
#define SM_Q    0        /* 32768: phase1 r0_2 ull[d][16tp]; phase3 qacc R4-swizzled */
#define SM_ZQM  32768    /* 256 x 34 = 8704 */
#define SM_A    41472    /* 32 q x 288 (t*9+c) = 9216 */
#define SM_BD   50688    /* 512 */
#define SM_BK   51200    /* 512 */
#define SM_M    51712    /* 32 */
#define SM_TOT  51744
#define SM_BYTES (SM_TOT*4)

typedef unsigned long long ull;

__device__ float g_iwt [DDIM * 256];        /* [d][q*8+c]                  */
__device__ float g_owT [NQ * CDIM * DDIM];  /* [q][c][d]                   */
__device__ float g_cbT [NQ * CDIM * KCB];   /* [q][c][k]                   */
__device__ float g_c2  [NQ * KCB];          /* |cb|^2                      */
__device__ float g_M   [NQ * NQ * 64];      /* [q2][p][c*8+cp] = -iw@ow    */
__device__ float g_Vc  [256];               /* [q*8+c] = iw^q . obpre^q    */
__device__ float g_obpre[NQ * DDIM];        /* prefix sum of ob (p < q)    */
__device__ float g_obsum[DDIM];             /* total sum of ob             */

__device__ __forceinline__ ull f2x(float lo, float hi) {
    ull r;
    asm("mov.b64 %0, {%1, %2};" : "=l"(r)
        : "r"(__float_as_uint(lo)), "r"(__float_as_uint(hi)));
    return r;
}
__device__ __forceinline__ void upk(ull v, float& lo, float& hi) {
    unsigned a, b;
    asm("mov.b64 {%0, %1}, %2;" : "=r"(a), "=r"(b) : "l"(v));
    lo = __uint_as_float(a); hi = __uint_as_float(b);
}
#define FMA2(D,A,B,C) asm("fma.rn.f32x2 %0, %1, %2, %3;" : "=l"(D) : "l"(A), "l"(B), "l"(C))

/* ---------- prep 0: ob prefix sums ---------- */
__global__ void prep0_kernel(const float* __restrict__ ob)
{
    int d = blockIdx.x * blockDim.x + threadIdx.x;
    if (d < DDIM) {
        float run = 0.f;
        for (int p = 0; p < NQ; p++) {
            g_obpre[p * DDIM + d] = run;
            run += ob[p * DDIM + d];
        }
        g_obsum[d] = run;
    }
}

/* ---------- prep 1: transposes + |cb|^2 ---------- */
__global__ void prep1_kernel(const float* __restrict__ iw,
                             const float* __restrict__ ow,
                             const float* __restrict__ cb)
{
    int idx = blockIdx.x * blockDim.x + threadIdx.x;
    int stride = gridDim.x * blockDim.x;
    for (int i = idx; i < DDIM * 256; i += stride) {
        int d = i >> 8, r = i & 255, q = r >> 3, c = r & 7;
        g_iwt[i] = iw[(q << 13) + (c << 10) + d];
    }
    for (int i = idx; i < NQ * CDIM * DDIM; i += stride) {
        int q = i >> 13, r = i & 8191, c = r >> 10, d = r & 1023;
        g_owT[i] = ow[(q << 13) + (d << 3) + c];
    }
    for (int i = idx; i < NQ * CDIM * KCB; i += stride) {
        int q = i >> 13, r = i & 8191, c = r >> 10, k = r & 1023;
        g_cbT[i] = cb[(q << 13) + (k << 3) + c];
    }
    for (int k = idx; k < NQ * KCB; k += stride) {
        const float4* row = (const float4*)(cb + (size_t)k * 8);
        float4 a = row[0], b4 = row[1];
        float p = fmaf(a.x, a.x, fmaf(a.y, a.y, fmaf(a.z, a.z, a.w * a.w)));
        float o = fmaf(b4.x, b4.x, fmaf(b4.y, b4.y, fmaf(b4.z, b4.z, b4.w * b4.w)));
        g_c2[k] = p + o;
    }
}

/* ---------- prep 2: M[q2][p] = -(iw^q2 @ ow^p), p < q2 ---------- */
__global__ void prep2_kernel(const float* __restrict__ iw,
                             const float* __restrict__ ow)
{
    int q2 = blockIdx.x >> 5, p = blockIdx.x & 31;
    if (p >= q2) return;
    __shared__ float ps[512];
    int tid = threadIdx.x;
    int pair = tid & 63;                 /* c*8+cp */
    int c = pair >> 3, cp = pair & 7;
    int slice = tid >> 6;                /* 0..7, 128 d each */
    const float* iwr = iw + (q2 << 13) + (c << 10) + slice * 128;
    const float* owr = ow + (p << 13) + cp + slice * 128 * 8;
    float s = 0.f;
    for (int d = 0; d < 128; d++) s = fmaf(iwr[d], owr[d * 8], s);
    ps[tid] = s;
    __syncthreads();
    if (tid < 64) {
        float t = 0.f;
        #pragma unroll
        for (int j = 0; j < 8; j++) t += ps[tid + j * 64];
        g_M[(q2 * 32 + p) * 64 + tid] = -t;
    }
}

/* ---------- prep 3: Vc[q][c] = iw^q[c] . obpre[q] ---------- */
__global__ void prep3_kernel(const float* __restrict__ iw)
{
    int q = blockIdx.x;
    __shared__ float ps[256];
    int tid = threadIdx.x;
    int c = tid >> 5, slice = tid & 31;
    const float* iwr = iw + (q << 13) + (c << 10) + slice * 32;
    const float* obr = g_obpre + (q << 10) + slice * 32;
    float s = 0.f;
    for (int d = 0; d < 32; d++) s = fmaf(iwr[d], obr[d], s);
    ps[tid] = s;
    __syncthreads();
    if (tid < 8) {
        float t = 0.f;
        #pragma unroll
        for (int j = 0; j < 32; j++) t += ps[tid * 32 + j];
        g_Vc[q * 8 + tid] = t;
    }
}

__global__ __launch_bounds__(NTH, 1)
void rvq_kernel(const float* __restrict__ z,
                const float* __restrict__ ibias,
                const float* __restrict__ cb,
                const int*   __restrict__ inlen,
                float* __restrict__ out,
                int wout, int widx, int wlen)
{
    extern __shared__ float sm[];
    ull*   r0u  = (ull*)(sm + SM_Q);
    float4* Q4  = (float4*)(sm + SM_Q);
    float* zqm  = sm + SM_ZQM;          /* [r][t] stride 34 */
    float* A    = sm + SM_A;            /* [q][t*9+c]       */
    float* bd_s = sm + SM_BD;
    int*   bk_s = (int*)(sm + SM_BK);
    float* m_s  = sm + SM_M;

    const int tid  = threadIdx.x;
    const int lane = tid & 31;
    const int w    = tid >> 5;          /* 0..15 */

    const int col0 = blockIdx.x * TILE;
    const int b    = col0 >> 12;
    const int t0   = col0 & (TDIM - 1);
    const int len  = inlen[b];

    const float* zb = z + (size_t)b * DDIM * TDIM + t0;

    if (tid < TILE) m_s[tid] = ((t0 + tid) < len) ? 1.0f : 0.0f;

    /* ---- init r0_2[d][16 tp] = packed z*mask ---- */
    #pragma unroll
    for (int it = 0; it < 16; it++) {
        int i = tid + it * NTH;         /* 0..8191 */
        int d = i >> 3, seg = i & 7;
        float4 v = *(const float4*)(zb + (size_t)d * TDIM + (seg << 2));
        int tb = t0 + (seg << 2);
        v.x = (tb + 0 < len) ? v.x : 0.0f;
        v.y = (tb + 1 < len) ? v.y : 0.0f;
        v.z = (tb + 2 < len) ? v.z : 0.0f;
        v.w = (tb + 3 < len) ? v.w : 0.0f;
        r0u[d * 16 + seg * 2]     = f2x(v.x, v.y);
        r0u[d * 16 + seg * 2 + 1] = f2x(v.z, v.w);
    }
    __syncthreads();

    /* ====== E0: A[q][t][c] = iw.r0 + ib - m*Vc ; warp = 16 rows ====== */
    {
        const int tp = lane & 15, rh = lane >> 4;
        const int rb = w * 16 + rh * 8;         /* 8 rows, q = 2w+rh */
        const int q  = 2 * w + rh;
        ull v[8];
        #pragma unroll
        for (int j = 0; j < 8; j++) v[j] = 0ull;
        const float* iwt = g_iwt + rb;
        #pragma unroll 4
        for (int d = 0; d < 1024; d++) {
            ull rr = r0u[d * 16 + tp];
            float4 wa = *(const float4*)(iwt + d * 256);
            float4 wb = *(const float4*)(iwt + d * 256 + 4);
            FMA2(v[0], f2x(wa.x, wa.x), rr, v[0]);
            FMA2(v[1], f2x(wa.y, wa.y), rr, v[1]);
            FMA2(v[2], f2x(wa.z, wa.z), rr, v[2]);
            FMA2(v[3], f2x(wa.w, wa.w), rr, v[3]);
            FMA2(v[4], f2x(wb.x, wb.x), rr, v[4]);
            FMA2(v[5], f2x(wb.y, wb.y), rr, v[5]);
            FMA2(v[6], f2x(wb.z, wb.z), rr, v[6]);
            FMA2(v[7], f2x(wb.w, wb.w), rr, v[7]);
        }
        float m0 = m_s[2 * tp], m1 = m_s[2 * tp + 1];
        float* Aq = A + q * 288;
        #pragma unroll
        for (int j = 0; j < 8; j++) {
            float lo, hi; upk(v[j], lo, hi);
            float ibv = ibias[q * 8 + j];
            float vc  = g_Vc[q * 8 + j];
            Aq[(2 * tp)     * 9 + j] = lo + ibv - m0 * vc;
            Aq[(2 * tp + 1) * 9 + j] = hi + ibv - m1 * vc;
        }
    }
    __syncthreads();

    /* ================== scan: P2 + select + scatter ================== */
    for (int q = 0; q < NQ; q++) {
        /* P2: warp w scans k in [64w,64w+64), lanes = t, cbT from L2 */
        {
            int t = lane;
            const float* Aq = A + q * 288 + t * 9;
            ull ed[8];
            #pragma unroll
            for (int c = 0; c < 8; c++) {
                float e = Aq[c];
                ed[c] = f2x(e, e);
            }
            const ull n2 = f2x(-2.0f, -2.0f);
            const float* cbt = g_cbT + ((size_t)q << 13);
            const float* c2g = g_c2 + ((size_t)q << 10);
            float best = 3.402823466e38f;
            int bk = 0;
            const int kb = w << 6;
            #pragma unroll 4
            for (int i = 0; i < 16; i++) {
                int k = kb + (i << 2);
                ull sA = 0ull, sB = 0ull;
                #pragma unroll
                for (int c = 0; c < 8; c++) {
                    ulonglong2 cv = *(const ulonglong2*)(cbt + c * 1024 + k);
                    FMA2(sA, cv.x, ed[c], sA);
                    FMA2(sB, cv.y, ed[c], sB);
                }
                ulonglong2 c2v = *(const ulonglong2*)(c2g + k);
                ull bA, bB;
                FMA2(bA, sA, n2, c2v.x);
                FMA2(bB, sB, n2, c2v.y);
                float da, db, dc, dd;
                upk(bA, da, db); upk(bB, dc, dd);
                if (da < best) { best = da; bk = k;     }
                if (db < best) { best = db; bk = k + 1; }
                if (dc < best) { best = dc; bk = k + 2; }
                if (dd < best) { best = dd; bk = k + 3; }
            }
            bd_s[w * 32 + t] = best;
            bk_s[w * 32 + t] = bk;
        }
        __syncthreads();

        /* select: final argmin + stage zqm (positive, masked) */
        if (tid < TILE) {
            int t = tid;
            float best = bd_s[t];
            int bk = bk_s[t];
            #pragma unroll
            for (int kc = 1; kc < 16; kc++) {
                float d2 = bd_s[kc * 32 + t];
                if (d2 < best) { best = d2; bk = bk_s[kc * 32 + t]; }
            }
            if (widx) out[BDT + q * NCOLS + col0 + t] = (float)bk;
            float mt = m_s[t];
            const float4* cr = (const float4*)(cb + (((size_t)q << 10) + bk) * 8);
            float4 ca = cr[0], cb4 = cr[1];
            float* zp = zqm + (q * 8) * 34 + t;
            zp[0 * 34] = ca.x * mt;  zp[1 * 34] = ca.y * mt;
            zp[2 * 34] = ca.z * mt;  zp[3 * 34] = ca.w * mt;
            zp[4 * 34] = cb4.x * mt; zp[5 * 34] = cb4.y * mt;
            zp[6 * 34] = cb4.z * mt; zp[7 * 34] = cb4.w * mt;
        }
        __syncthreads();

        /* scatter: A[q2] += M~[q2][q] . zqm^q   (M~ pre-negated) */
        {
            int nf = (NQ - 1 - q) * 8;
            float zq8[8];
            #pragma unroll
            for (int cp = 0; cp < 8; cp++)
                zq8[cp] = zqm[(q * 8 + cp) * 34 + lane];
            for (int idx = w; idx < nf; idx += 16) {
                int q2 = q + 1 + (idx >> 3), c = idx & 7;
                const float* Mr = g_M + (q2 * 32 + q) * 64 + c * 8;
                float4 m0 = *(const float4*)Mr;
                float4 m1 = *(const float4*)(Mr + 4);
                float s = m0.x * zq8[0];
                s = fmaf(m0.y, zq8[1], s);
                s = fmaf(m0.z, zq8[2], s);
                s = fmaf(m0.w, zq8[3], s);
                s = fmaf(m1.x, zq8[4], s);
                s = fmaf(m1.y, zq8[5], s);
                s = fmaf(m1.z, zq8[6], s);
                s = fmaf(m1.w, zq8[7], s);
                A[q2 * 288 + lane * 9 + c] += s;
            }
        }
        __syncthreads();
    }

    /* ====== qout GEMM: qacc = OW @ ZQM + obsum*m (overlays r0) ====== */
    #pragma unroll
    for (int it = 0; it < 16; it++) {
        int i = tid + it * NTH;
        int d = i >> 3, tq = i & 7;
        float ob = g_obsum[d];
        float4 mv = *(const float4*)(m_s + (tq << 2));
        Q4[d * 8 + (tq ^ (d & 7))] =
            make_float4(ob * mv.x, ob * mv.y, ob * mv.z, ob * mv.w);
    }
    __syncthreads();
    {
        const int tg = w >> 1;          /* t-quad 0..7 */
        const int dg = w & 1;           /* d-half      */
        for (int qq = 0; qq < NQ; qq += 2) {
            ull zqA[16], zqB[16];
            #pragma unroll
            for (int e = 0; e < 16; e++) {
                const float* zp = zqm + (qq * 8 + e) * 34 + tg * 4;
                float2 p0 = *(const float2*)zp;
                float2 p1 = *(const float2*)(zp + 2);
                zqA[e] = f2x(p0.x, p0.y);
                zqB[e] = f2x(p1.x, p1.y);
            }
            const float* owb = g_owT + ((size_t)qq << 13);
            #pragma unroll 4
            for (int i = 0; i < 16; i++) {
                int d = dg * 512 + lane + (i << 5);
                int slot = d * 8 + (tg ^ (d & 7));
                ulonglong2 r = *(const ulonglong2*)&Q4[slot];
                #pragma unroll
                for (int e = 0; e < 16; e++) {
                    float wv = owb[e * 1024 + d];
                    ull wd = f2x(wv, wv);
                    FMA2(r.x, wd, zqA[e], r.x);
                    FMA2(r.y, wd, zqB[e], r.y);
                }
                *(ulonglong2*)&Q4[slot] = r;
            }
        }
    }
    __syncthreads();

    /* ---- epilogue: out = qacc ---- */
    if (wout) {
        #pragma unroll
        for (int it = 0; it < 16; it++) {
            int i = tid + it * NTH;
            int d = i >> 3, tq = i & 7;
            float4 v = Q4[d * 8 + (tq ^ (d & 7))];
            *(float4*)(out + (size_t)b * DDIM * TDIM + (size_t)d * TDIM + t0 + (tq << 2)) = v;
        }
    }
    if (wlen && blockIdx.x == 0 && tid < BDIMS)
        out[BDT + NQBT + tid] = (float)inlen[tid];
}

extern "C" void kernel_launch(void* const* d_in, const int* in_sizes, int n_in,
                              void* d_out, int out_size)
{
    const float* z   = (const float*)d_in[0];
    const float* iw  = (const float*)d_in[1];
    const float* ib  = (const float*)d_in[2];
    const float* ow  = (const float*)d_in[3];
    const float* ob  = (const float*)d_in[4];
    const float* cbk = (const float*)d_in[5];
    const int* inlen = (const int*)d_in[6];
    float* out = (float*)d_out;

    cudaFuncSetAttribute(rvq_kernel, cudaFuncAttributeMaxDynamicSharedMemorySize, SM_BYTES);

    int wout = (out_size >= BDT) ? 1 : 0;
    int widx = (out_size >= BDT + NQBT) ? 1 : 0;
    int wlen = (out_size >= BDT + NQBT + BDIMS) ? 1 : 0;

    prep0_kernel<<<4, 256>>>(ob);
    prep1_kernel<<<256, 512>>>(iw, ow, cbk);
    prep2_kernel<<<NQ * NQ, 512>>>(iw, ow);
    prep3_kernel<<<NQ, 256>>>(iw);
    rvq_kernel<<<NCOLS / TILE, NTH, SM_BYTES>>>(z, ib, cbk, inlen,
                                               out, wout, widx, wlen);
}